// round 1
// baseline (speedup 1.0000x reference)
#include <cuda_runtime.h>

#define NB   8
#define TOUT 256
#define TIN  512
#define LH   128     // L
#define G4   512     // 4*L
#define DIN  128
#define DATT 128

#define OUT_X_ELEMS (NB*TOUT*(LH+DATT))   // 524288
#define OUT_H_OFF   (OUT_X_ELEMS)
#define OUT_C_OFF   (OUT_X_ELEMS + NB*LH)

// scratch (allocation-free: device globals)
__device__ float g_keys[NB*TIN*LH];     // 2 MB
__device__ float g_xz[NB*TOUT*G4];      // 4 MB
__device__ float g_q[NB*TOUT*LH];       // 1 MB
__device__ float g_attn[NB*TOUT*TIN];   // 4 MB

__device__ __forceinline__ float sigm_f(float x) {
    // 1/(1+e^-x) via MUFU EX2+RCP, ~2^-22 accurate, saturates correctly
    return 1.0f / (1.0f + __expf(-x));
}
__device__ __forceinline__ float tanh_f(float x) {
    // tanh(x) = 1 - 2/(1+e^{2x}); stable at both tails (inf -> 1, 0 -> -1)
    return 1.0f - 2.0f / (1.0f + __expf(2.0f * x));
}

// ---------------------------------------------------------------------------
// K1: keys[b,k,:] = attended[b,k,:] @ W1 + b1      (4096 rows x 128)
// ---------------------------------------------------------------------------
__global__ void __launch_bounds__(128) keys_kernel(
    const float* __restrict__ att, const float* __restrict__ W1,
    const float* __restrict__ b1, float* __restrict__ keys)
{
    int row = blockIdx.x;                 // b*TIN + k
    __shared__ float a[DATT];
    a[threadIdx.x] = att[row * DATT + threadIdx.x];
    __syncthreads();
    int j = threadIdx.x;
    float acc = b1[j];
    #pragma unroll 8
    for (int l = 0; l < DATT; l++)
        acc += a[l] * W1[l * LH + j];
    keys[row * LH + j] = acc;
}

// ---------------------------------------------------------------------------
// K2: xz[b,t,:] = inputs[b,t,:] @ Wk + bias        (2048 rows x 512)
// ---------------------------------------------------------------------------
__global__ void __launch_bounds__(512) xz_kernel(
    const float* __restrict__ inp, const float* __restrict__ Wk,
    const float* __restrict__ bias, float* __restrict__ xz)
{
    int row = blockIdx.x;                 // b*TOUT + t
    __shared__ float a[DIN];
    if (threadIdx.x < DIN) a[threadIdx.x] = inp[row * DIN + threadIdx.x];
    __syncthreads();
    int j = threadIdx.x;
    float acc = bias[j];
    #pragma unroll 8
    for (int d = 0; d < DIN; d++)
        acc += a[d] * Wk[d * G4 + j];
    xz[row * G4 + j] = acc;
}

// ---------------------------------------------------------------------------
// K3: LSTM scan. One CTA per batch, 512 threads (thread = gate column).
//     h in smem; Wr streamed from global (L1-resident across steps).
//     Writes x into out[...,0:128] each step; h_T, c_T at the end.
// ---------------------------------------------------------------------------
__global__ void __launch_bounds__(512) lstm_kernel(
    const float* __restrict__ xz, const float* __restrict__ Wr,
    float* __restrict__ out)
{
    int b = blockIdx.x;
    int j = threadIdx.x;                  // 0..511 gate column
    __shared__ float h_s[LH];
    __shared__ float z_s[G4];
    if (j < LH) h_s[j] = 0.0f;
    float c = 0.0f;                       // live in threads j<128
    __syncthreads();

    const float* xzb = xz + b * TOUT * G4;

    for (int t = 0; t < TOUT; t++) {
        float acc = xzb[t * G4 + j];
        #pragma unroll
        for (int k = 0; k < LH; k += 4) {
            float4 h4 = *reinterpret_cast<const float4*>(&h_s[k]);
            acc += h4.x * Wr[(k + 0) * G4 + j];
            acc += h4.y * Wr[(k + 1) * G4 + j];
            acc += h4.z * Wr[(k + 2) * G4 + j];
            acc += h4.w * Wr[(k + 3) * G4 + j];
        }
        z_s[j] = acc;
        __syncthreads();
        if (j < LH) {
            float zi = z_s[j];
            float zf = z_s[LH + j];
            float zg = z_s[2 * LH + j];
            float zo = z_s[3 * LH + j];
            c = sigm_f(zf) * c + sigm_f(zi) * tanh_f(zg);
            float h = sigm_f(zo) * tanh_f(c);
            h_s[j] = h;
            out[(b * TOUT + t) * (LH + DATT) + j] = h;   // x part of out
        }
        __syncthreads();
    }
    if (j < LH) {
        out[OUT_H_OFF + b * LH + j] = h_s[j];
        out[OUT_C_OFF + b * LH + j] = c;
    }
}

// ---------------------------------------------------------------------------
// K4: q[b,t,:] = x[b,t,:] @ W2 + b2  (x read back from out buffer)
// ---------------------------------------------------------------------------
__global__ void __launch_bounds__(128) q_kernel(
    const float* __restrict__ out, const float* __restrict__ W2,
    const float* __restrict__ b2, float* __restrict__ q)
{
    int row = blockIdx.x;                 // b*TOUT + t
    __shared__ float a[LH];
    a[threadIdx.x] = out[row * (LH + DATT) + threadIdx.x];
    __syncthreads();
    int j = threadIdx.x;
    float acc = b2[j];
    #pragma unroll 8
    for (int l = 0; l < LH; l++)
        acc += a[l] * W2[l * LH + j];
    q[row * LH + j] = acc;
}

// ---------------------------------------------------------------------------
// K5: scores + softmax. One CTA per (b,t) row; warp per key, lanes split L.
//     scores[b,t,k] = sum_l w3[l]*tanh(keys[b,k,l]+q[b,t,l]); b3 drops out
//     of softmax. Writes normalized attention weights.
// ---------------------------------------------------------------------------
__global__ void __launch_bounds__(256) attn_kernel(
    const float* __restrict__ keys, const float* __restrict__ q,
    const float* __restrict__ W3, float* __restrict__ attn)
{
    int row = blockIdx.x;                 // b*TOUT + t
    int b   = row >> 8;
    int tid = threadIdx.x;
    int w   = tid >> 5;
    int lane = tid & 31;

    __shared__ float sc[TIN];
    __shared__ float red[256];

    float4 qv  = *reinterpret_cast<const float4*>(&q[row * LH + lane * 4]);
    float4 w3v = *reinterpret_cast<const float4*>(&W3[lane * 4]);

    const float* kb = keys + b * TIN * LH;
    for (int k = w; k < TIN; k += 8) {
        float4 kv = *reinterpret_cast<const float4*>(&kb[k * LH + lane * 4]);
        float s;
        s  = w3v.x * tanh_f(kv.x + qv.x);
        s += w3v.y * tanh_f(kv.y + qv.y);
        s += w3v.z * tanh_f(kv.z + qv.z);
        s += w3v.w * tanh_f(kv.w + qv.w);
        #pragma unroll
        for (int off = 16; off >= 1; off >>= 1)
            s += __shfl_xor_sync(0xffffffffu, s, off);
        if (lane == 0) sc[k] = s;
    }
    __syncthreads();

    // softmax over 512 with 256 threads
    red[tid] = fmaxf(sc[tid], sc[tid + 256]);
    __syncthreads();
    #pragma unroll
    for (int s = 128; s >= 1; s >>= 1) {
        if (tid < s) red[tid] = fmaxf(red[tid], red[tid + s]);
        __syncthreads();
    }
    float mx = red[0];
    __syncthreads();

    float e0 = __expf(sc[tid] - mx);
    float e1 = __expf(sc[tid + 256] - mx);
    red[tid] = e0 + e1;
    __syncthreads();
    #pragma unroll
    for (int s = 128; s >= 1; s >>= 1) {
        if (tid < s) red[tid] += red[tid + s];
        __syncthreads();
    }
    float inv = 1.0f / red[0];

    attn[row * TIN + tid]       = e0 * inv;
    attn[row * TIN + 256 + tid] = e1 * inv;
}

// ---------------------------------------------------------------------------
// K6: weighted[b,t,:] = attn[b,t,:] @ attended[b,:,:]
//     Tile of 16 q-rows per CTA; attn tile staged in smem (32 KB).
// ---------------------------------------------------------------------------
__global__ void __launch_bounds__(256) weighted_kernel(
    const float* __restrict__ attn, const float* __restrict__ att,
    float* __restrict__ out)
{
    int b  = blockIdx.y;
    int q0 = blockIdx.x * 16;
    int tid = threadIdx.x;

    __shared__ float a_s[16][TIN];
    for (int i = tid; i < 16 * TIN; i += 256) {
        int r = i >> 9, kk = i & 511;
        a_s[r][kk] = attn[(b * TOUT + q0 + r) * TIN + kk];
    }
    __syncthreads();

    int d = tid & 127;
    int g = tid >> 7;                     // 0/1 -> rows g*8..g*8+7
    float acc[8];
    #pragma unroll
    for (int i = 0; i < 8; i++) acc[i] = 0.0f;

    const float* ap = att + b * TIN * DATT + d;
    #pragma unroll 4
    for (int k = 0; k < TIN; k++) {
        float av = ap[k * DATT];
        #pragma unroll
        for (int i = 0; i < 8; i++)
            acc[i] += a_s[g * 8 + i][k] * av;
    }
    #pragma unroll
    for (int i = 0; i < 8; i++)
        out[(b * TOUT + q0 + g * 8 + i) * (LH + DATT) + LH + d] = acc[i];
}

// ---------------------------------------------------------------------------
extern "C" void kernel_launch(void* const* d_in, const int* in_sizes, int n_in,
                              void* d_out, int out_size)
{
    const float* inputs   = (const float*)d_in[0];   // (8,256,128)
    const float* attended = (const float*)d_in[1];   // (8,512,128)
    const float* Wk       = (const float*)d_in[2];   // (128,512)
    const float* Wr       = (const float*)d_in[3];   // (128,512)
    const float* lbias    = (const float*)d_in[4];   // (512,)
    const float* W1       = (const float*)d_in[5];   // (128,128)
    const float* b1       = (const float*)d_in[6];   // (128,)
    const float* W2       = (const float*)d_in[7];   // (128,128)
    const float* b2       = (const float*)d_in[8];   // (128,)
    const float* W3       = (const float*)d_in[9];   // (128,1)
    // b3 (d_in[10]) cancels in softmax — unused.
    float* out = (float*)d_out;

    float* keys = g_keys;
    float* xz   = g_xz;
    float* q    = g_q;
    float* attn = g_attn;
    // device-symbol addresses are valid directly in kernels; fetch via
    // cudaGetSymbolAddress is not graph-needed — pass symbols through kernels.

    keys_kernel<<<NB * TIN, 128>>>(attended, W1, b1, g_keys);
    xz_kernel<<<NB * TOUT, 512>>>(inputs, Wk, lbias, g_xz);
    lstm_kernel<<<NB, 512>>>(g_xz, Wr, out);
    q_kernel<<<NB * TOUT, 128>>>(out, W2, b2, g_q);
    attn_kernel<<<NB * TOUT, 256>>>(g_keys, g_q, W3, g_attn);
    {
        dim3 grid(16, NB);
        weighted_kernel<<<grid, 256>>>(g_attn, attended, out);
    }
    (void)keys; (void)xz; (void)q; (void)attn;
    (void)in_sizes; (void)n_in; (void)out_size;
}

// round 2
// speedup vs baseline: 1.0966x; 1.0966x over previous
#include <cuda_runtime.h>

#define NB   8
#define TOUT 256
#define TIN  512
#define LH   128     // L
#define G4   512     // 4*L
#define DIN  128
#define DATT 128

#define OUT_X_ELEMS (NB*TOUT*(LH+DATT))   // 524288
#define OUT_H_OFF   (OUT_X_ELEMS)
#define OUT_C_OFF   (OUT_X_ELEMS + NB*LH)

#define KREG 64                    // Wr k-rows held in registers
#define KSM  (LH - KREG)           // Wr k-rows streamed from smem
#define LSTM_DSMEM (KSM * G4 * 4)  // 131072 B dynamic smem

// scratch (allocation-free: device globals)
__device__ float g_keys[NB*TIN*LH];     // 2 MB
__device__ float g_xz[NB*TOUT*G4];      // 4 MB
__device__ float g_q[NB*TOUT*LH];       // 1 MB
__device__ float g_attn[NB*TOUT*TIN];   // 4 MB

__device__ __forceinline__ float sigm_f(float x) {
    return 1.0f / (1.0f + __expf(-x));          // accurate (EX2+RCP)
}
__device__ __forceinline__ float tanh_f(float x) {
    return 1.0f - 2.0f / (1.0f + __expf(2.0f * x));   // accurate, tail-stable
}
__device__ __forceinline__ float tanh_hw(float x) {
    float y;
    asm("tanh.approx.f32 %0, %1;" : "=f"(y) : "f"(x));  // 1 MUFU
    return y;
}

// ---------------------------------------------------------------------------
// K1: keys[b,k,:] = attended[b,k,:] @ W1 + b1      (4096 rows x 128)
// ---------------------------------------------------------------------------
__global__ void __launch_bounds__(128) keys_kernel(
    const float* __restrict__ att, const float* __restrict__ W1,
    const float* __restrict__ b1, float* __restrict__ keys)
{
    int row = blockIdx.x;
    __shared__ float a[DATT];
    a[threadIdx.x] = att[row * DATT + threadIdx.x];
    __syncthreads();
    int j = threadIdx.x;
    float acc = b1[j];
    #pragma unroll 8
    for (int l = 0; l < DATT; l++)
        acc += a[l] * W1[l * LH + j];
    keys[row * LH + j] = acc;
}

// ---------------------------------------------------------------------------
// K2: xz[b,t,:] = inputs[b,t,:] @ Wk + bias        (2048 rows x 512)
// ---------------------------------------------------------------------------
__global__ void __launch_bounds__(512) xz_kernel(
    const float* __restrict__ inp, const float* __restrict__ Wk,
    const float* __restrict__ bias, float* __restrict__ xz)
{
    int row = blockIdx.x;
    __shared__ float a[DIN];
    if (threadIdx.x < DIN) a[threadIdx.x] = inp[row * DIN + threadIdx.x];
    __syncthreads();
    int j = threadIdx.x;
    float acc = bias[j];
    #pragma unroll 8
    for (int d = 0; d < DIN; d++)
        acc += a[d] * Wk[d * G4 + j];
    xz[row * G4 + j] = acc;
}

// ---------------------------------------------------------------------------
// K3: LSTM scan. One CTA per batch, 512 threads (thread = gate column).
//     Wr rows 0..KREG-1 live in registers (loaded once); rows KREG..127 live
//     in dynamic smem (coalesced conflict-free LDS). Zero global traffic for
//     weights inside the scan. xz row prefetched one step ahead.
// ---------------------------------------------------------------------------
__global__ void __launch_bounds__(512, 1) lstm_kernel(
    const float* __restrict__ xz, const float* __restrict__ Wr,
    float* __restrict__ out)
{
    int b = blockIdx.x;
    int j = threadIdx.x;                  // gate column 0..511
    __shared__ float h_s[LH];
    __shared__ float z_s[G4];
    extern __shared__ float w_s[];        // [KSM][G4]

    // preload smem slice of Wr (k = KREG..127), coalesced
    #pragma unroll 4
    for (int kk = 0; kk < KSM; kk++)
        w_s[kk * G4 + j] = Wr[(KREG + kk) * G4 + j];

    // preload register slice of Wr (k = 0..KREG-1)
    float wr[KREG];
    #pragma unroll
    for (int k = 0; k < KREG; k++)
        wr[k] = Wr[k * G4 + j];

    if (j < LH) h_s[j] = 0.0f;
    float c = 0.0f;
    __syncthreads();

    const float* xzb = xz + b * TOUT * G4;
    float xnext = xzb[j];

    for (int t = 0; t < TOUT; t++) {
        float acc0 = xnext;
        float acc1 = 0.0f;
        if (t + 1 < TOUT) xnext = xzb[(t + 1) * G4 + j];  // hide L2 latency

        #pragma unroll
        for (int kk = 0; kk < KREG / 4; kk++) {
            float4 h4 = *reinterpret_cast<const float4*>(&h_s[kk * 4]);
            acc0 += h4.x * wr[kk * 4 + 0];
            acc1 += h4.y * wr[kk * 4 + 1];
            acc0 += h4.z * wr[kk * 4 + 2];
            acc1 += h4.w * wr[kk * 4 + 3];
        }
        #pragma unroll
        for (int kk = 0; kk < KSM / 4; kk++) {
            float4 h4 = *reinterpret_cast<const float4*>(&h_s[KREG + kk * 4]);
            acc0 += h4.x * w_s[(kk * 4 + 0) * G4 + j];
            acc1 += h4.y * w_s[(kk * 4 + 1) * G4 + j];
            acc0 += h4.z * w_s[(kk * 4 + 2) * G4 + j];
            acc1 += h4.w * w_s[(kk * 4 + 3) * G4 + j];
        }
        z_s[j] = acc0 + acc1;
        __syncthreads();
        if (j < LH) {
            float zi = z_s[j];
            float zf = z_s[LH + j];
            float zg = z_s[2 * LH + j];
            float zo = z_s[3 * LH + j];
            c = sigm_f(zf) * c + sigm_f(zi) * tanh_f(zg);
            float h = sigm_f(zo) * tanh_f(c);
            h_s[j] = h;
            out[(b * TOUT + t) * (LH + DATT) + j] = h;
        }
        __syncthreads();
    }
    if (j < LH) {
        out[OUT_H_OFF + b * LH + j] = h_s[j];
        out[OUT_C_OFF + b * LH + j] = c;
    }
}

// ---------------------------------------------------------------------------
// K4: q[b,t,:] = x[b,t,:] @ W2 + b2
// ---------------------------------------------------------------------------
__global__ void __launch_bounds__(128) q_kernel(
    const float* __restrict__ out, const float* __restrict__ W2,
    const float* __restrict__ b2, float* __restrict__ q)
{
    int row = blockIdx.x;
    __shared__ float a[LH];
    a[threadIdx.x] = out[row * (LH + DATT) + threadIdx.x];
    __syncthreads();
    int j = threadIdx.x;
    float acc = b2[j];
    #pragma unroll 8
    for (int l = 0; l < LH; l++)
        acc += a[l] * W2[l * LH + j];
    q[row * LH + j] = acc;
}

// ---------------------------------------------------------------------------
// K5: scores + softmax (HW tanh.approx for the 134M-element tanh).
// ---------------------------------------------------------------------------
__global__ void __launch_bounds__(256) attn_kernel(
    const float* __restrict__ keys, const float* __restrict__ q,
    const float* __restrict__ W3, float* __restrict__ attn)
{
    int row = blockIdx.x;
    int b   = row >> 8;
    int tid = threadIdx.x;
    int w   = tid >> 5;
    int lane = tid & 31;

    __shared__ float sc[TIN];
    __shared__ float red[256];

    float4 qv  = *reinterpret_cast<const float4*>(&q[row * LH + lane * 4]);
    float4 w3v = *reinterpret_cast<const float4*>(&W3[lane * 4]);

    const float* kb = keys + b * TIN * LH;
    for (int k = w; k < TIN; k += 8) {
        float4 kv = *reinterpret_cast<const float4*>(&kb[k * LH + lane * 4]);
        float s;
        s  = w3v.x * tanh_hw(kv.x + qv.x);
        s += w3v.y * tanh_hw(kv.y + qv.y);
        s += w3v.z * tanh_hw(kv.z + qv.z);
        s += w3v.w * tanh_hw(kv.w + qv.w);
        #pragma unroll
        for (int off = 16; off >= 1; off >>= 1)
            s += __shfl_xor_sync(0xffffffffu, s, off);
        if (lane == 0) sc[k] = s;
    }
    __syncthreads();

    red[tid] = fmaxf(sc[tid], sc[tid + 256]);
    __syncthreads();
    #pragma unroll
    for (int s = 128; s >= 1; s >>= 1) {
        if (tid < s) red[tid] = fmaxf(red[tid], red[tid + s]);
        __syncthreads();
    }
    float mx = red[0];
    __syncthreads();

    float e0 = __expf(sc[tid] - mx);
    float e1 = __expf(sc[tid + 256] - mx);
    red[tid] = e0 + e1;
    __syncthreads();
    #pragma unroll
    for (int s = 128; s >= 1; s >>= 1) {
        if (tid < s) red[tid] += red[tid + s];
        __syncthreads();
    }
    float inv = 1.0f / red[0];

    attn[row * TIN + tid]       = e0 * inv;
    attn[row * TIN + 256 + tid] = e1 * inv;
}

// ---------------------------------------------------------------------------
// K6: weighted[b,t,:] = attn[b,t,:] @ attended[b,:,:]
// ---------------------------------------------------------------------------
__global__ void __launch_bounds__(256) weighted_kernel(
    const float* __restrict__ attn, const float* __restrict__ att,
    float* __restrict__ out)
{
    int b  = blockIdx.y;
    int q0 = blockIdx.x * 16;
    int tid = threadIdx.x;

    __shared__ float a_s[16][TIN];
    for (int i = tid; i < 16 * TIN; i += 256) {
        int r = i >> 9, kk = i & 511;
        a_s[r][kk] = attn[(b * TOUT + q0 + r) * TIN + kk];
    }
    __syncthreads();

    int d = tid & 127;
    int g = tid >> 7;
    float acc[8];
    #pragma unroll
    for (int i = 0; i < 8; i++) acc[i] = 0.0f;

    const float* ap = att + b * TIN * DATT + d;
    #pragma unroll 4
    for (int k = 0; k < TIN; k++) {
        float av = ap[k * DATT];
        #pragma unroll
        for (int i = 0; i < 8; i++)
            acc[i] += a_s[g * 8 + i][k] * av;
    }
    #pragma unroll
    for (int i = 0; i < 8; i++)
        out[(b * TOUT + q0 + g * 8 + i) * (LH + DATT) + LH + d] = acc[i];
}

// ---------------------------------------------------------------------------
extern "C" void kernel_launch(void* const* d_in, const int* in_sizes, int n_in,
                              void* d_out, int out_size)
{
    const float* inputs   = (const float*)d_in[0];
    const float* attended = (const float*)d_in[1];
    const float* Wk       = (const float*)d_in[2];
    const float* Wr       = (const float*)d_in[3];
    const float* lbias    = (const float*)d_in[4];
    const float* W1       = (const float*)d_in[5];
    const float* b1       = (const float*)d_in[6];
    const float* W2       = (const float*)d_in[7];
    const float* b2       = (const float*)d_in[8];
    const float* W3       = (const float*)d_in[9];
    float* out = (float*)d_out;

    cudaFuncSetAttribute(lstm_kernel,
                         cudaFuncAttributeMaxDynamicSharedMemorySize, LSTM_DSMEM);

    keys_kernel<<<NB * TIN, 128>>>(attended, W1, b1, g_keys);
    xz_kernel<<<NB * TOUT, 512>>>(inputs, Wk, lbias, g_xz);
    lstm_kernel<<<NB, 512, LSTM_DSMEM>>>(g_xz, Wr, out);
    q_kernel<<<NB * TOUT, 128>>>(out, W2, b2, g_q);
    attn_kernel<<<NB * TOUT, 256>>>(g_keys, g_q, W3, g_attn);
    {
        dim3 grid(16, NB);
        weighted_kernel<<<grid, 256>>>(g_attn, attended, out);
    }
    (void)in_sizes; (void)n_in; (void)out_size;
}

// round 3
// speedup vs baseline: 2.5462x; 2.3218x over previous
#include <cuda_runtime.h>
#include <cuda_fp16.h>

#define NB   8
#define TOUT 256
#define TIN  512
#define LH   128
#define G4   512
#define DIN  128
#define DATT 128

#define OUT_X_ELEMS (NB*TOUT*(LH+DATT))
#define OUT_H_OFF   (OUT_X_ELEMS)
#define OUT_C_OFF   (OUT_X_ELEMS + NB*LH)

#define KREG 80
#define KSM  (LH - KREG)            // 48
#define LSTM_DSMEM (KSM * G4 * 4)   // 98304 B

#define AQ 8                        // q-rows per attn CTA
// attn smem layout (bytes)
#define A_KEYS_OFF 0
#define A_KEYS_SZ  (128 * 65 * 4)          // half2[128][65] = 33280
#define A_QH_OFF   (A_KEYS_OFF + A_KEYS_SZ)
#define A_QH_SZ    (AQ * 64 * 4)           // 2048
#define A_W3_OFF   (A_QH_OFF + A_QH_SZ)
#define A_W3_SZ    (64 * 4)                // 256
#define A_SC_OFF   (A_W3_OFF + A_W3_SZ)
#define A_SC_SZ    (AQ * 512 * 4)          // 16384
#define ATTN_DSMEM (A_SC_OFF + A_SC_SZ)    // 51968

__device__ float g_keys[NB*TIN*LH];
__device__ float g_xz[NB*TOUT*G4];
__device__ float g_q[NB*TOUT*LH];
__device__ float g_attn[NB*TOUT*TIN];

__device__ __forceinline__ float tanh_hw(float x) {
    float y;
    asm("tanh.approx.f32 %0, %1;" : "=f"(y) : "f"(x));
    return y;
}
__device__ __forceinline__ float sigm_hw(float x) {
    return fmaf(0.5f, tanh_hw(0.5f * x), 0.5f);
}
__device__ __forceinline__ __half2 tanh_h2(__half2 x) {
    unsigned r, xi = *reinterpret_cast<unsigned*>(&x);
    asm("tanh.approx.f16x2 %0, %1;" : "=r"(r) : "r"(xi));
    return *reinterpret_cast<__half2*>(&r);
}

// ---------------------------------------------------------------------------
// K1 (launch 1): fused keys + xz projections. 128 threads/CTA.
//   bid < NB*TIN          : keys row (1 col/thread)
//   else                  : xz row (4 cols/thread)
// ---------------------------------------------------------------------------
__global__ void __launch_bounds__(128) proj_kernel(
    const float* __restrict__ att, const float* __restrict__ W1,
    const float* __restrict__ b1,  float* __restrict__ keys,
    const float* __restrict__ inp, const float* __restrict__ Wk,
    const float* __restrict__ lbias, float* __restrict__ xz)
{
    int bid = blockIdx.x;
    int j = threadIdx.x;
    __shared__ float a[DIN];
    if (bid < NB * TIN) {
        int row = bid;
        a[j] = att[row * DATT + j];
        __syncthreads();
        float acc = b1[j];
        #pragma unroll 8
        for (int l = 0; l < DATT; l++)
            acc += a[l] * W1[l * LH + j];
        keys[row * LH + j] = acc;
    } else {
        int row = bid - NB * TIN;
        a[j] = inp[row * DIN + j];
        __syncthreads();
        float a0 = lbias[j], a1 = lbias[j + 128],
              a2 = lbias[j + 256], a3 = lbias[j + 384];
        #pragma unroll 4
        for (int d = 0; d < DIN; d++) {
            float v = a[d];
            const float* wr = Wk + d * G4;
            a0 += v * wr[j];
            a1 += v * wr[j + 128];
            a2 += v * wr[j + 256];
            a3 += v * wr[j + 384];
        }
        float* o = xz + row * G4;
        o[j] = a0; o[j + 128] = a1; o[j + 256] = a2; o[j + 384] = a3;
    }
}

// ---------------------------------------------------------------------------
// K2 (launch 2): LSTM scan. 1 CTA/batch, 512 threads.
//   Wr rows 0..KREG-1 in registers, rows KREG..127 in dynamic smem.
// ---------------------------------------------------------------------------
__global__ void __launch_bounds__(512, 1) lstm_kernel(
    const float* __restrict__ xz, const float* __restrict__ Wr,
    float* __restrict__ out)
{
    int b = blockIdx.x;
    int j = threadIdx.x;
    __shared__ float h_s[LH];
    __shared__ float z_s[G4];
    extern __shared__ float w_s[];        // [KSM][G4]

    #pragma unroll 4
    for (int kk = 0; kk < KSM; kk++)
        w_s[kk * G4 + j] = Wr[(KREG + kk) * G4 + j];

    float wr[KREG];
    #pragma unroll
    for (int k = 0; k < KREG; k++)
        wr[k] = Wr[k * G4 + j];

    if (j < LH) h_s[j] = 0.0f;
    float c = 0.0f;
    __syncthreads();

    const float* xzb = xz + b * TOUT * G4;
    float xnext = xzb[j];

    for (int t = 0; t < TOUT; t++) {
        float acc0 = xnext;
        float acc1 = 0.0f;
        if (t + 1 < TOUT) xnext = xzb[(t + 1) * G4 + j];

        #pragma unroll
        for (int kk = 0; kk < KREG / 4; kk++) {
            float4 h4 = *reinterpret_cast<const float4*>(&h_s[kk * 4]);
            acc0 += h4.x * wr[kk * 4 + 0];
            acc1 += h4.y * wr[kk * 4 + 1];
            acc0 += h4.z * wr[kk * 4 + 2];
            acc1 += h4.w * wr[kk * 4 + 3];
        }
        #pragma unroll
        for (int kk = 0; kk < KSM / 4; kk++) {
            float4 h4 = *reinterpret_cast<const float4*>(&h_s[KREG + kk * 4]);
            acc0 += h4.x * w_s[(kk * 4 + 0) * G4 + j];
            acc1 += h4.y * w_s[(kk * 4 + 1) * G4 + j];
            acc0 += h4.z * w_s[(kk * 4 + 2) * G4 + j];
            acc1 += h4.w * w_s[(kk * 4 + 3) * G4 + j];
        }
        z_s[j] = acc0 + acc1;
        __syncthreads();
        if (j < LH) {
            float zi = z_s[j];
            float zf = z_s[LH + j];
            float zg = z_s[2 * LH + j];
            float zo = z_s[3 * LH + j];
            c = sigm_hw(zf) * c + sigm_hw(zi) * tanh_hw(zg);
            float h = sigm_hw(zo) * tanh_hw(c);
            h_s[j] = h;
            out[(b * TOUT + t) * (LH + DATT) + j] = h;
        }
        __syncthreads();
    }
    if (j < LH) {
        out[OUT_H_OFF + b * LH + j] = h_s[j];
        out[OUT_C_OFF + b * LH + j] = c;
    }
}

// ---------------------------------------------------------------------------
// K3 (launch 3): q = x @ W2 + b2
// ---------------------------------------------------------------------------
__global__ void __launch_bounds__(128) q_kernel(
    const float* __restrict__ out, const float* __restrict__ W2,
    const float* __restrict__ b2, float* __restrict__ q)
{
    int row = blockIdx.x;
    __shared__ float a[LH];
    a[threadIdx.x] = out[row * (LH + DATT) + threadIdx.x];
    __syncthreads();
    int j = threadIdx.x;
    float acc = b2[j];
    #pragma unroll 8
    for (int l = 0; l < LH; l++)
        acc += a[l] * W2[l * LH + j];
    q[row * LH + j] = acc;
}

// ---------------------------------------------------------------------------
// K4 (launch 4 — profiled slot): scores + softmax, f16x2 tanh, no shuffles
// in the score phase. CTA = (b, 8 q-rows), 512 threads, dynamic smem.
//   thread = (ql = tid>>6, key slot kk = tid&63); 2 keys/thread per 128-chunk.
// ---------------------------------------------------------------------------
__global__ void __launch_bounds__(512, 2) attn_kernel(
    const float* __restrict__ keys, const float* __restrict__ q,
    const float* __restrict__ W3, float* __restrict__ attn)
{
    extern __shared__ char sm[];
    __half2* keys_h = reinterpret_cast<__half2*>(sm + A_KEYS_OFF);  // [128][65]
    __half2* qh     = reinterpret_cast<__half2*>(sm + A_QH_OFF);    // [AQ][64]
    __half2* w3h    = reinterpret_cast<__half2*>(sm + A_W3_OFF);    // [64]
    float*   sc     = reinterpret_cast<float*>(sm + A_SC_OFF);      // [AQ][512]

    int b  = blockIdx.y;
    int q0 = blockIdx.x * AQ;
    int tid = threadIdx.x;

    // stage q (as half2) and w3
    for (int i = tid; i < AQ * 64; i += 512) {
        int r = i >> 6, l2 = i & 63;
        float2 v = *reinterpret_cast<const float2*>(&q[(b * TOUT + q0 + r) * LH + 2 * l2]);
        qh[r * 64 + l2] = __floats2half2_rn(v.x, v.y);
    }
    if (tid < 64) {
        float2 v = *reinterpret_cast<const float2*>(&W3[2 * tid]);
        w3h[tid] = __floats2half2_rn(v.x, v.y);
    }

    int ql = tid >> 6;            // 0..7
    int kk = tid & 63;            // key slot within chunk half
    const float* kb = keys + b * TIN * LH;

    for (int c = 0; c < 4; c++) {
        __syncthreads();          // protect keys_h overwrite (and qh on c==0)
        for (int i = tid; i < 128 * 64; i += 512) {
            int k = i >> 6, l2 = i & 63;
            float2 v = *reinterpret_cast<const float2*>(&kb[(c * 128 + k) * LH + 2 * l2]);
            keys_h[k * 65 + l2] = __floats2half2_rn(v.x, v.y);
        }
        __syncthreads();

        float acc0 = 0.0f, acc1 = 0.0f;
        const __half2* qrow = qh + ql * 64;
        #pragma unroll 4
        for (int l2 = 0; l2 < 64; l2++) {
            __half2 qv = qrow[l2];
            __half2 wv = w3h[l2];
            __half2 k0 = keys_h[kk * 65 + l2];
            __half2 k1 = keys_h[(kk + 64) * 65 + l2];
            __half2 p0 = __hmul2(tanh_h2(__hadd2(k0, qv)), wv);
            __half2 p1 = __hmul2(tanh_h2(__hadd2(k1, qv)), wv);
            acc0 += __low2float(p0) + __high2float(p0);
            acc1 += __low2float(p1) + __high2float(p1);
        }
        sc[ql * 512 + c * 128 + kk]      = acc0;
        sc[ql * 512 + c * 128 + kk + 64] = acc1;
    }
    __syncthreads();

    // softmax: warp w (< AQ) handles row w (512 values, 16/lane)
    int w = tid >> 5, lane = tid & 31;
    if (w < AQ) {
        const float* row = sc + w * 512;
        float v[16], mx = -1e30f;
        #pragma unroll
        for (int i = 0; i < 16; i++) {
            v[i] = row[lane + 32 * i];
            mx = fmaxf(mx, v[i]);
        }
        #pragma unroll
        for (int off = 16; off >= 1; off >>= 1)
            mx = fmaxf(mx, __shfl_xor_sync(0xffffffffu, mx, off));
        float s = 0.0f;
        #pragma unroll
        for (int i = 0; i < 16; i++) {
            v[i] = __expf(v[i] - mx);
            s += v[i];
        }
        #pragma unroll
        for (int off = 16; off >= 1; off >>= 1)
            s += __shfl_xor_sync(0xffffffffu, s, off);
        float inv = 1.0f / s;
        float* orow = attn + (b * TOUT + q0 + w) * TIN;
        #pragma unroll
        for (int i = 0; i < 16; i++)
            orow[lane + 32 * i] = v[i] * inv;
    }
}

// ---------------------------------------------------------------------------
// K5 (launch 5): weighted = attn @ attended
// ---------------------------------------------------------------------------
__global__ void __launch_bounds__(256) weighted_kernel(
    const float* __restrict__ attn, const float* __restrict__ att,
    float* __restrict__ out)
{
    int b  = blockIdx.y;
    int q0 = blockIdx.x * 16;
    int tid = threadIdx.x;

    __shared__ float a_s[16][TIN];
    for (int i = tid; i < 16 * TIN; i += 256) {
        int r = i >> 9, kk = i & 511;
        a_s[r][kk] = attn[(b * TOUT + q0 + r) * TIN + kk];
    }
    __syncthreads();

    int d = tid & 127;
    int g = tid >> 7;
    float acc[8];
    #pragma unroll
    for (int i = 0; i < 8; i++) acc[i] = 0.0f;

    const float* ap = att + b * TIN * DATT + d;
    #pragma unroll 4
    for (int k = 0; k < TIN; k++) {
        float av = ap[k * DATT];
        #pragma unroll
        for (int i = 0; i < 8; i++)
            acc[i] += a_s[g * 8 + i][k] * av;
    }
    #pragma unroll
    for (int i = 0; i < 8; i++)
        out[(b * TOUT + q0 + g * 8 + i) * (LH + DATT) + LH + d] = acc[i];
}

// ---------------------------------------------------------------------------
extern "C" void kernel_launch(void* const* d_in, const int* in_sizes, int n_in,
                              void* d_out, int out_size)
{
    const float* inputs   = (const float*)d_in[0];
    const float* attended = (const float*)d_in[1];
    const float* Wk       = (const float*)d_in[2];
    const float* Wr       = (const float*)d_in[3];
    const float* lbias    = (const float*)d_in[4];
    const float* W1       = (const float*)d_in[5];
    const float* b1       = (const float*)d_in[6];
    const float* W2       = (const float*)d_in[7];
    const float* b2       = (const float*)d_in[8];
    const float* W3       = (const float*)d_in[9];
    float* out = (float*)d_out;

    cudaFuncSetAttribute(lstm_kernel,
                         cudaFuncAttributeMaxDynamicSharedMemorySize, LSTM_DSMEM);
    cudaFuncSetAttribute(attn_kernel,
                         cudaFuncAttributeMaxDynamicSharedMemorySize, ATTN_DSMEM);

    proj_kernel<<<NB * TIN + NB * TOUT, 128>>>(attended, W1, b1, g_keys,
                                               inputs, Wk, lbias, g_xz);
    lstm_kernel<<<NB, 512, LSTM_DSMEM>>>(g_xz, Wr, out);
    q_kernel<<<NB * TOUT, 128>>>(out, W2, b2, g_q);
    {
        dim3 grid(TOUT / AQ, NB);
        attn_kernel<<<grid, 512, ATTN_DSMEM>>>(g_keys, g_q, W3, g_attn);
    }
    {
        dim3 grid(16, NB);
        weighted_kernel<<<grid, 256>>>(g_attn, attended, out);
    }
    (void)in_sizes; (void)n_in; (void)out_size;
}